// round 7
// baseline (speedup 1.0000x reference)
#include <cuda_runtime.h>
#include <cuda_bf16.h>
#include <math.h>
#include <stdint.h>

// Problem constants: B=4, S=2048, N_EMBD=1024, E=8, K=2, D_FF=4096
#define T_TOK 8192
#define D_IN  1024
#define D_FF  4096
#define NE    8

// ---------------------------------------------------------------------------
// Scratch (__device__ globals only)
// ---------------------------------------------------------------------------
__device__ int      g_cnt[NE];
__device__ int      g_fill[NE];
__device__ int      g_off[NE];
__device__ int      g_top[T_TOK * 2];
__device__ float    g_wt[T_TOK * 2];
__device__ int      g_tok[T_TOK * 2];
__device__ float    g_pw[T_TOK * 2];

// Pre-split bf16 planes (hi + lo) for everything the GEMMs touch.
__device__ __nv_bfloat16 g_xhi[(size_t)T_TOK * D_IN];
__device__ __nv_bfloat16 g_xlo[(size_t)T_TOK * D_IN];
__device__ __nv_bfloat16 g_w1hi[(size_t)NE * D_IN * D_FF];
__device__ __nv_bfloat16 g_w1lo[(size_t)NE * D_IN * D_FF];
__device__ __nv_bfloat16 g_w2hi[(size_t)NE * D_FF * D_IN];
__device__ __nv_bfloat16 g_w2lo[(size_t)NE * D_FF * D_IN];
__device__ __nv_bfloat16 g_hhi[(size_t)T_TOK * 2 * D_FF];
__device__ __nv_bfloat16 g_hlo[(size_t)T_TOK * 2 * D_FF];

// ---------------------------------------------------------------------------
// Portable PTX helpers (sm_80+ only: mma.sync, ldmatrix, cp.async)
// ---------------------------------------------------------------------------
__device__ __forceinline__ uint32_t smem_u32(const void* p) {
    uint32_t a;
    asm("{ .reg .u64 t; cvta.to.shared.u64 t, %1; cvt.u32.u64 %0, t; }"
        : "=r"(a) : "l"(p));
    return a;
}
__device__ __forceinline__ void ldsm4(uint32_t* r, uint32_t addr) {
    asm volatile("ldmatrix.sync.aligned.m8n8.x4.shared.b16 {%0,%1,%2,%3}, [%4];"
        : "=r"(r[0]), "=r"(r[1]), "=r"(r[2]), "=r"(r[3]) : "r"(addr));
}
__device__ __forceinline__ void ldsm4t(uint32_t* r, uint32_t addr) {
    asm volatile("ldmatrix.sync.aligned.m8n8.x4.trans.shared.b16 {%0,%1,%2,%3}, [%4];"
        : "=r"(r[0]), "=r"(r[1]), "=r"(r[2]), "=r"(r[3]) : "r"(addr));
}
__device__ __forceinline__ void mma16816(float* d, const uint32_t* a,
                                         uint32_t b0, uint32_t b1) {
    asm volatile(
        "mma.sync.aligned.m16n8k16.row.col.f32.bf16.bf16.f32 "
        "{%0,%1,%2,%3}, {%4,%5,%6,%7}, {%8,%9}, {%0,%1,%2,%3};"
        : "+f"(d[0]), "+f"(d[1]), "+f"(d[2]), "+f"(d[3])
        : "r"(a[0]), "r"(a[1]), "r"(a[2]), "r"(a[3]), "r"(b0), "r"(b1));
}
__device__ __forceinline__ void cp16(uint32_t dst, const void* src) {
    asm volatile("cp.async.cg.shared.global [%0], [%1], 16;"
                 :: "r"(dst), "l"(src) : "memory");
}
__device__ __forceinline__ void cp_commit() {
    asm volatile("cp.async.commit_group;" ::: "memory");
}
template<int N> __device__ __forceinline__ void cp_wait() {
    asm volatile("cp.async.wait_group %0;" :: "n"(N) : "memory");
}

// bf16 hi/lo split of a float4 -> two packed bf16x2 words each
__device__ __forceinline__ void bf16_split4(float4 v, uint2& hi, uint2& lo) {
    __nv_bfloat16 h0 = __float2bfloat16(v.x);
    __nv_bfloat16 h1 = __float2bfloat16(v.y);
    __nv_bfloat16 h2 = __float2bfloat16(v.z);
    __nv_bfloat16 h3 = __float2bfloat16(v.w);
    hi.x = ((uint32_t)__bfloat16_as_ushort(h1) << 16) | __bfloat16_as_ushort(h0);
    hi.y = ((uint32_t)__bfloat16_as_ushort(h3) << 16) | __bfloat16_as_ushort(h2);
    __nv_bfloat16 l0 = __float2bfloat16(v.x - __bfloat162float(h0));
    __nv_bfloat16 l1 = __float2bfloat16(v.y - __bfloat162float(h1));
    __nv_bfloat16 l2 = __float2bfloat16(v.z - __bfloat162float(h2));
    __nv_bfloat16 l3 = __float2bfloat16(v.w - __bfloat162float(h3));
    lo.x = ((uint32_t)__bfloat16_as_ushort(l1) << 16) | __bfloat16_as_ushort(l0);
    lo.y = ((uint32_t)__bfloat16_as_ushort(l3) << 16) | __bfloat16_as_ushort(l2);
}

// ---------------------------------------------------------------------------
// SMEM: FOUR 32 KB stages (4-deep cp.async ring). Per stage:
//   [0,8192)      A_hi : 128 rows x 32 bf16 (64B rows, swizzled)
//   [8192,16384)  A_lo
//   [16384,24576) B_hi : 4 subtiles [32k x 32n] (64B rows, swizzled)
//   [24576,32768) B_lo
// Swizzle: chunk' = chunk ^ ((row>>1)&3)
// ---------------------------------------------------------------------------
#define NSTAGE 4
#define BUF_BYTES 32768
#define SMEM_BYTES (NSTAGE * BUF_BYTES)   // 128 KB
#define OFF_AHI 0
#define OFF_ALO 8192
#define OFF_BHI 16384
#define OFF_BLO 24576

__device__ __forceinline__ int swz(int row, int chunk) {
    return row * 64 + ((chunk ^ ((row >> 1) & 3)) << 4);
}

// ---------------------------------------------------------------------------
// bf16x3 HMMA GEMM, zero-conversion hot loop, 4-stage cp.async pipeline.
//  GATHER=true : A = (g_xhi,g_xlo)[g_tok], epilogue relu+bias -> g_hhi/g_hlo
//  GATHER=false: A = (g_hhi,g_hlo),        epilogue bias, *w -> atomicAdd out
// CTA tile 128x128, K-chunk 32, 256 threads (8 warps, 64x32 warp tiles).
// ---------------------------------------------------------------------------
template<int K_TOTAL, int B_STRIDE, bool GATHER>
__global__ __launch_bounds__(256)
void moe_mma_kernel(const __nv_bfloat16* __restrict__ Bhi,
                    const __nv_bfloat16* __restrict__ Blo,
                    const float* __restrict__ bias,
                    float* __restrict__ out) {
    const int e   = blockIdx.z;
    const int cnt = g_cnt[e];
    const int m0  = blockIdx.y * 128;
    if (m0 >= cnt) return;
    const int n0   = blockIdx.x * 128;
    const int base = g_off[e];

    extern __shared__ char smem[];
    const uint32_t sb = smem_u32(smem);
    const int t    = threadIdx.x;
    const int lane = t & 31;
    const int wid  = t >> 5;
    const int wm   = wid >> 2;     // 0..1
    const int wn   = wid & 3;      // 0..3

    // ---- cp.async staging assignments ----------------------------------
    const int rowA = t >> 1;
    const int colA = (t & 1) * 16;
    const int cA0  = (t & 1) * 2;
    const __nv_bfloat16 *ahi_row, *alo_row;
    {
        int m = min(m0 + rowA, cnt - 1);
        if (GATHER) {
            size_t r = (size_t)g_tok[base + m] * D_IN;
            ahi_row = g_xhi + r; alo_row = g_xlo + r;
        } else {
            size_t r = (size_t)(base + m) * D_FF;
            ahi_row = g_hhi + r; alo_row = g_hlo + r;
        }
    }
    const int kB   = t >> 3;
    const int nb   = (t & 7) * 16;
    const int bsub = nb >> 5;
    const int cB0  = ((nb & 31) >> 3);
    const size_t wb_off = (size_t)e * K_TOTAL * B_STRIDE + n0 + nb;
    const __nv_bfloat16* bhi_p = Bhi + wb_off;
    const __nv_bfloat16* blo_p = Blo + wb_off;

    const int NCH = K_TOTAL / 32;

    // issue stage for chunk index ch2 (or an empty commit group past the end)
    auto issue_stage = [&](int ch2) {
        if (ch2 < NCH) {
            const int k0 = ch2 * 32;
            const uint32_t s = sb + (ch2 & (NSTAGE - 1)) * BUF_BYTES;
            {
                uint32_t d0 = s + OFF_AHI + swz(rowA, cA0);
                uint32_t d1 = s + OFF_AHI + swz(rowA, cA0 + 1);
                cp16(d0, ahi_row + k0 + colA);
                cp16(d1, ahi_row + k0 + colA + 8);
                cp16(d0 + (OFF_ALO - OFF_AHI), alo_row + k0 + colA);
                cp16(d1 + (OFF_ALO - OFF_AHI), alo_row + k0 + colA + 8);
            }
            {
                uint32_t d0 = s + OFF_BHI + bsub * 2048 + swz(kB, cB0);
                uint32_t d1 = s + OFF_BHI + bsub * 2048 + swz(kB, cB0 + 1);
                const __nv_bfloat16* sh = bhi_p + (size_t)(k0 + kB) * B_STRIDE;
                const __nv_bfloat16* sl = blo_p + (size_t)(k0 + kB) * B_STRIDE;
                cp16(d0, sh);
                cp16(d1, sh + 8);
                cp16(d0 + (OFF_BLO - OFF_BHI), sl);
                cp16(d1 + (OFF_BLO - OFF_BHI), sl + 8);
            }
        }
        cp_commit();   // always commit: uniform group accounting
    };

    float acc[4][4][4];
#pragma unroll
    for (int i = 0; i < 4; i++)
#pragma unroll
        for (int j = 0; j < 4; j++)
#pragma unroll
            for (int r = 0; r < 4; r++) acc[i][j][r] = 0.f;

    const int ml   = lane & 15;
    const int chhi = lane >> 4;

    auto mma_stage = [&](int buf) {
        const uint32_t sbuf = sb + buf * BUF_BYTES;
#pragma unroll
        for (int ks = 0; ks < 2; ks++) {
            uint32_t ah[4][4], al[4][4], bh[2][4], bl[2][4];
#pragma unroll
            for (int i = 0; i < 4; i++) {
                int m = wm * 64 + i * 16 + ml;
                int cc = (ks * 2 + chhi) ^ ((m >> 1) & 3);
                uint32_t ad = sbuf + m * 64 + cc * 16;
                ldsm4(ah[i], ad + OFF_AHI);
                ldsm4(al[i], ad + OFF_ALO);
            }
#pragma unroll
            for (int p = 0; p < 2; p++) {
                int k = ks * 16 + ml;
                int cc = (p * 2 + chhi) ^ ((k >> 1) & 3);
                uint32_t bd = sbuf + wn * 2048 + k * 64 + cc * 16;
                ldsm4t(bh[p], bd + OFF_BHI);
                ldsm4t(bl[p], bd + OFF_BLO);
            }
#pragma unroll
            for (int i = 0; i < 4; i++)
#pragma unroll
                for (int j = 0; j < 4; j++) {
                    uint32_t b0h = bh[j >> 1][(j & 1) * 2];
                    uint32_t b1h = bh[j >> 1][(j & 1) * 2 + 1];
                    uint32_t b0l = bl[j >> 1][(j & 1) * 2];
                    uint32_t b1l = bl[j >> 1][(j & 1) * 2 + 1];
                    mma16816(acc[i][j], ah[i], b0h, b1h);   // hi*hi
                    mma16816(acc[i][j], ah[i], b0l, b1l);   // hi*lo
                    mma16816(acc[i][j], al[i], b0h, b1h);   // lo*hi
                }
        }
    };

    // ---- 4-stage pipelined main loop, ONE barrier per chunk -------------
    issue_stage(0);
    issue_stage(1);
    issue_stage(2);
    for (int ch = 0; ch < NCH; ch++) {
        cp_wait<NSTAGE - 2>();     // stage ch resident
        __syncthreads();           // all warps done with stage ch-1 (= ch+3 ring slot)
        issue_stage(ch + 3);       // prefetch into just-freed slot
        mma_stage(ch & (NSTAGE - 1));
    }

    // ---- epilogue -------------------------------------------------------
    const float* be = bias + (size_t)e * B_STRIDE;
#pragma unroll
    for (int i = 0; i < 4; i++) {
        int mA = m0 + wm * 64 + i * 16 + (lane >> 2);
#pragma unroll
        for (int half = 0; half < 2; half++) {     // rows mA and mA+8
            int m = mA + half * 8;
            if (m >= cnt) continue;
            size_t hrow = 0;
            float* op = nullptr;
            float  rw = 0.f;
            if (GATHER) {
                hrow = (size_t)(base + m) * D_FF;
            } else {
                op = out + (size_t)g_tok[base + m] * D_IN;
                rw = g_pw[base + m];
            }
#pragma unroll
            for (int j = 0; j < 4; j++) {
                int n = n0 + wn * 32 + j * 8 + (lane & 3) * 2;
                float v0 = acc[i][j][half * 2 + 0] + be[n];
                float v1 = acc[i][j][half * 2 + 1] + be[n + 1];
                if (GATHER) {
                    v0 = fmaxf(v0, 0.f); v1 = fmaxf(v1, 0.f);
                    __nv_bfloat16 h0 = __float2bfloat16(v0);
                    __nv_bfloat16 h1 = __float2bfloat16(v1);
                    __nv_bfloat16 l0 = __float2bfloat16(v0 - __bfloat162float(h0));
                    __nv_bfloat16 l1 = __float2bfloat16(v1 - __bfloat162float(h1));
                    uint32_t hp = ((uint32_t)__bfloat16_as_ushort(h1) << 16)
                                | __bfloat16_as_ushort(h0);
                    uint32_t lp = ((uint32_t)__bfloat16_as_ushort(l1) << 16)
                                | __bfloat16_as_ushort(l0);
                    *(uint32_t*)(g_hhi + hrow + n) = hp;
                    *(uint32_t*)(g_hlo + hrow + n) = lp;
                } else {
                    atomicAdd(&op[n],     rw * v0);
                    atomicAdd(&op[n + 1], rw * v1);
                }
            }
        }
    }
}

// ---------------------------------------------------------------------------
// Pre-split: fp32 array -> hi/lo bf16 planes (vectorized, grid-stride)
// ---------------------------------------------------------------------------
__global__ void split_kernel(const float* __restrict__ src,
                             __nv_bfloat16* __restrict__ hi,
                             __nv_bfloat16* __restrict__ lo, int n4) {
    int i = blockIdx.x * blockDim.x + threadIdx.x;
    for (; i < n4; i += gridDim.x * blockDim.x) {
        float4 v = ((const float4*)src)[i];
        uint2 h, l; bf16_split4(v, h, l);
        ((uint2*)hi)[i] = h;
        ((uint2*)lo)[i] = l;
    }
}

// ---------------------------------------------------------------------------
// Router / packing (unchanged)
// ---------------------------------------------------------------------------
__global__ void zero_counts_kernel() {
    int i = threadIdx.x;
    if (i < NE) { g_cnt[i] = 0; g_fill[i] = 0; }
}

__global__ void router_kernel(const float* __restrict__ x,
                              const float* __restrict__ Wr,
                              const float* __restrict__ br) {
    int gw   = (blockIdx.x * blockDim.x + threadIdx.x) >> 5;
    int lane = threadIdx.x & 31;
    if (gw >= T_TOK) return;

    const float* xr = x + (size_t)gw * D_IN;
    float acc[NE];
#pragma unroll
    for (int e = 0; e < NE; e++) acc[e] = 0.f;

    for (int d = lane; d < D_IN; d += 32) {
        float xv = xr[d];
        float4 a = *(const float4*)(Wr + d * NE);
        float4 b = *(const float4*)(Wr + d * NE + 4);
        acc[0] += xv * a.x; acc[1] += xv * a.y; acc[2] += xv * a.z; acc[3] += xv * a.w;
        acc[4] += xv * b.x; acc[5] += xv * b.y; acc[6] += xv * b.z; acc[7] += xv * b.w;
    }
#pragma unroll
    for (int e = 0; e < NE; e++) {
#pragma unroll
        for (int o = 16; o > 0; o >>= 1)
            acc[e] += __shfl_xor_sync(0xffffffffu, acc[e], o);
    }
    if (lane == 0) {
        float lg[NE];
#pragma unroll
        for (int e = 0; e < NE; e++) lg[e] = acc[e] + br[e];
        int i0 = 0;
#pragma unroll
        for (int e = 1; e < NE; e++) if (lg[e] > lg[i0]) i0 = e;
        int i1 = (i0 == 0) ? 1 : 0;
#pragma unroll
        for (int e = 0; e < NE; e++) if (e != i0 && lg[e] > lg[i1]) i1 = e;
        float ex  = expf(lg[i1] - lg[i0]);
        float inv = 1.0f / (1.0f + ex);
        g_top[2 * gw + 0] = i0;  g_top[2 * gw + 1] = i1;
        g_wt [2 * gw + 0] = inv; g_wt [2 * gw + 1] = ex * inv;
        atomicAdd(&g_cnt[i0], 1);
        atomicAdd(&g_cnt[i1], 1);
    }
}

__global__ void scan_kernel() {
    int s = 0;
    for (int e = 0; e < NE; e++) { g_off[e] = s; s += g_cnt[e]; }
}

__global__ void fill_kernel() {
    int t = blockIdx.x * blockDim.x + threadIdx.x;
    if (t >= T_TOK) return;
#pragma unroll
    for (int s = 0; s < 2; s++) {
        int e = g_top[2 * t + s];
        int p = g_off[e] + atomicAdd(&g_fill[e], 1);
        g_tok[p] = t;
        g_pw[p]  = g_wt[2 * t + s];
    }
}

// ---------------------------------------------------------------------------
// launch
// ---------------------------------------------------------------------------
extern "C" void kernel_launch(void* const* d_in, const int* in_sizes, int n_in,
                              void* d_out, int out_size) {
    const float* x   = (const float*)d_in[0];
    const float* Wr  = (const float*)d_in[1];
    const float* br  = (const float*)d_in[2];
    const float* W1  = (const float*)d_in[3];
    const float* b1  = (const float*)d_in[4];
    const float* W2  = (const float*)d_in[5];
    const float* b2  = (const float*)d_in[6];
    float*       out = (float*)d_out;

    cudaFuncSetAttribute(moe_mma_kernel<1024, 4096, true>,
                         cudaFuncAttributeMaxDynamicSharedMemorySize, SMEM_BYTES);
    cudaFuncSetAttribute(moe_mma_kernel<4096, 1024, false>,
                         cudaFuncAttributeMaxDynamicSharedMemorySize, SMEM_BYTES);

    __nv_bfloat16 *xhi, *xlo, *w1hi, *w1lo, *w2hi, *w2lo;
    cudaGetSymbolAddress((void**)&xhi,  g_xhi);
    cudaGetSymbolAddress((void**)&xlo,  g_xlo);
    cudaGetSymbolAddress((void**)&w1hi, g_w1hi);
    cudaGetSymbolAddress((void**)&w1lo, g_w1lo);
    cudaGetSymbolAddress((void**)&w2hi, g_w2hi);
    cudaGetSymbolAddress((void**)&w2lo, g_w2lo);

    cudaMemsetAsync(out, 0, (size_t)out_size * sizeof(float));
    zero_counts_kernel<<<1, 32>>>();
    router_kernel<<<T_TOK / 8, 256>>>(x, Wr, br);
    scan_kernel<<<1, 1>>>();
    fill_kernel<<<T_TOK / 256, 256>>>();

    // One-time (per launch) fp32 -> hi/lo bf16 plane splits
    split_kernel<<<1024, 256>>>(x,  xhi,  xlo,  (T_TOK * D_IN) / 4);
    split_kernel<<<2048, 256>>>(W1, w1hi, w1lo, (NE * D_IN * D_FF) / 4);
    split_kernel<<<2048, 256>>>(W2, w2hi, w2lo, (NE * D_FF * D_IN) / 4);

    // FFN1: h = relu(x_g @ W1 + b1) -> hi/lo planes; K=1024
    moe_mma_kernel<1024, 4096, true>
        <<<dim3(D_FF / 128, T_TOK / 128, NE), 256, SMEM_BYTES>>>(w1hi, w1lo, b1, out);
    // FFN2: out += w * (h @ W2 + b2); K=4096
    moe_mma_kernel<4096, 1024, false>
        <<<dim3(D_IN / 128, T_TOK / 128, NE), 256, SMEM_BYTES>>>(w2hi, w2lo, b2, out);
}

// round 8
// speedup vs baseline: 1.6202x; 1.6202x over previous
#include <cuda_runtime.h>
#include <cuda_fp16.h>
#include <math.h>
#include <stdint.h>

// Problem constants: B=4, S=2048, N_EMBD=1024, E=8, K=2, D_FF=4096
#define T_TOK 8192
#define D_IN  1024
#define D_FF  4096
#define NE    8

// ---------------------------------------------------------------------------
// Scratch (__device__ globals only)
// ---------------------------------------------------------------------------
__device__ int      g_cnt[NE];
__device__ int      g_fill[NE];
__device__ int      g_off[NE];
__device__ int      g_top[T_TOK * 2];
__device__ float    g_wt[T_TOK * 2];
__device__ int      g_tok[T_TOK * 2];
__device__ float    g_pw[T_TOK * 2];

// fp16 operand planes: A-side single plane (rounded), B-side hi/lo split.
__device__ __half g_xf [(size_t)T_TOK * D_IN];
__device__ __half g_w1hi[(size_t)NE * D_IN * D_FF];
__device__ __half g_w1lo[(size_t)NE * D_IN * D_FF];
__device__ __half g_w2hi[(size_t)NE * D_FF * D_IN];
__device__ __half g_w2lo[(size_t)NE * D_FF * D_IN];
__device__ __half g_hf [(size_t)T_TOK * 2 * D_FF];   // hidden acts, fp16 (134 MB)

// ---------------------------------------------------------------------------
// Portable PTX helpers (sm_80+ only: mma.sync, ldmatrix, cp.async)
// ---------------------------------------------------------------------------
__device__ __forceinline__ uint32_t smem_u32(const void* p) {
    uint32_t a;
    asm("{ .reg .u64 t; cvta.to.shared.u64 t, %1; cvt.u32.u64 %0, t; }"
        : "=r"(a) : "l"(p));
    return a;
}
__device__ __forceinline__ void ldsm4(uint32_t* r, uint32_t addr) {
    asm volatile("ldmatrix.sync.aligned.m8n8.x4.shared.b16 {%0,%1,%2,%3}, [%4];"
        : "=r"(r[0]), "=r"(r[1]), "=r"(r[2]), "=r"(r[3]) : "r"(addr));
}
__device__ __forceinline__ void ldsm4t(uint32_t* r, uint32_t addr) {
    asm volatile("ldmatrix.sync.aligned.m8n8.x4.trans.shared.b16 {%0,%1,%2,%3}, [%4];"
        : "=r"(r[0]), "=r"(r[1]), "=r"(r[2]), "=r"(r[3]) : "r"(addr));
}
__device__ __forceinline__ void mma16816(float* d, const uint32_t* a,
                                         uint32_t b0, uint32_t b1) {
    asm volatile(
        "mma.sync.aligned.m16n8k16.row.col.f32.f16.f16.f32 "
        "{%0,%1,%2,%3}, {%4,%5,%6,%7}, {%8,%9}, {%0,%1,%2,%3};"
        : "+f"(d[0]), "+f"(d[1]), "+f"(d[2]), "+f"(d[3])
        : "r"(a[0]), "r"(a[1]), "r"(a[2]), "r"(a[3]), "r"(b0), "r"(b1));
}
__device__ __forceinline__ void cp16(uint32_t dst, const void* src) {
    asm volatile("cp.async.cg.shared.global [%0], [%1], 16;"
                 :: "r"(dst), "l"(src) : "memory");
}
__device__ __forceinline__ void cp_commit() {
    asm volatile("cp.async.commit_group;" ::: "memory");
}
template<int N> __device__ __forceinline__ void cp_wait() {
    asm volatile("cp.async.wait_group %0;" :: "n"(N) : "memory");
}

// fp16 round of float4 -> packed 2x(2xfp16)
__device__ __forceinline__ uint2 f16_round4(float4 v) {
    uint2 r;
    __half2 p0 = __floats2half2_rn(v.x, v.y);
    __half2 p1 = __floats2half2_rn(v.z, v.w);
    r.x = *(uint32_t*)&p0;
    r.y = *(uint32_t*)&p1;
    return r;
}
// fp16 hi/lo split of float4
__device__ __forceinline__ void f16_split4(float4 v, uint2& hi, uint2& lo) {
    __half h0 = __float2half_rn(v.x), h1 = __float2half_rn(v.y);
    __half h2 = __float2half_rn(v.z), h3 = __float2half_rn(v.w);
    __half l0 = __float2half_rn(v.x - __half2float(h0));
    __half l1 = __float2half_rn(v.y - __half2float(h1));
    __half l2 = __float2half_rn(v.z - __half2float(h2));
    __half l3 = __float2half_rn(v.w - __half2float(h3));
    hi.x = ((uint32_t)__half_as_ushort(h1) << 16) | __half_as_ushort(h0);
    hi.y = ((uint32_t)__half_as_ushort(h3) << 16) | __half_as_ushort(h2);
    lo.x = ((uint32_t)__half_as_ushort(l1) << 16) | __half_as_ushort(l0);
    lo.y = ((uint32_t)__half_as_ushort(l3) << 16) | __half_as_ushort(l2);
}

// ---------------------------------------------------------------------------
// SMEM: two 24 KB stages (proven R6 2-stage loop shape). Per stage:
//   [0,8192)      A   : 128 rows x 32 fp16 (64B rows, swizzled)
//   [8192,16384)  B_hi: 4 subtiles [32k x 32n] (64B rows, swizzled)
//   [16384,24576) B_lo
// Swizzle: chunk' = chunk ^ ((row>>1)&3)  (16B chunks, 4 per 64B row)
// ---------------------------------------------------------------------------
#define BUF_BYTES 24576
#define SMEM_BYTES (2 * BUF_BYTES)     // 48 KB -> 2 CTAs/SM fit
#define OFF_A   0
#define OFF_BHI 8192
#define OFF_BLO 16384

__device__ __forceinline__ int swz(int row, int chunk) {
    return row * 64 + ((chunk ^ ((row >> 1) & 3)) << 4);
}

// ---------------------------------------------------------------------------
// fp16x2 HMMA GEMM: D = A * (Bhi + Blo), A rounded fp16, B split exactly.
//  GATHER=true : A = g_xf[g_tok], epilogue relu+bias -> g_hf (fp16)   K=1024
//  GATHER=false: A = g_hf,        epilogue bias, *w -> atomicAdd out  K=4096
// CTA tile 128x128, K-chunk 32, 256 threads (8 warps, 64x32 warp tiles).
// ---------------------------------------------------------------------------
template<int K_TOTAL, int B_STRIDE, bool GATHER>
__global__ __launch_bounds__(256, 2)
void moe_mma_kernel(const __half* __restrict__ Bhi,
                    const __half* __restrict__ Blo,
                    const float* __restrict__ bias,
                    float* __restrict__ out) {
    const int e   = blockIdx.z;
    const int cnt = g_cnt[e];
    const int m0  = blockIdx.y * 128;
    if (m0 >= cnt) return;
    const int n0   = blockIdx.x * 128;
    const int base = g_off[e];

    extern __shared__ char smem[];
    const uint32_t sb = smem_u32(smem);
    const int t    = threadIdx.x;
    const int lane = t & 31;
    const int wid  = t >> 5;
    const int wm   = wid >> 2;     // 0..1
    const int wn   = wid & 3;      // 0..3

    // ---- cp.async staging assignments ----------------------------------
    // A: 2 threads/row: rowA = t>>1, each thread 32B = 16 fp16 elems
    const int rowA = t >> 1;
    const int colA = (t & 1) * 16;
    const int cA0  = (t & 1) * 2;
    const __half* a_row;
    {
        int m = min(m0 + rowA, cnt - 1);
        if (GATHER) a_row = g_xf + (size_t)g_tok[base + m] * D_IN;
        else        a_row = g_hf + (size_t)(base + m) * D_FF;
    }
    // B: 8 threads/row: kB = t>>3 (0..31), each thread 32B = 16 n-elems
    const int kB   = t >> 3;
    const int nb   = (t & 7) * 16;
    const int bsub = nb >> 5;
    const int cB0  = ((nb & 31) >> 3);
    const size_t wb_off = (size_t)e * K_TOTAL * B_STRIDE + n0 + nb;
    const __half* bhi_p = Bhi + wb_off;
    const __half* blo_p = Blo + wb_off;

    auto issue_stage = [&](int k0, int buf) {
        const uint32_t s = sb + buf * BUF_BYTES;
        {   // A plane
            uint32_t d0 = s + OFF_A + swz(rowA, cA0);
            uint32_t d1 = s + OFF_A + swz(rowA, cA0 + 1);
            cp16(d0, a_row + k0 + colA);
            cp16(d1, a_row + k0 + colA + 8);
        }
        {   // B planes
            uint32_t d0 = s + OFF_BHI + bsub * 2048 + swz(kB, cB0);
            uint32_t d1 = s + OFF_BHI + bsub * 2048 + swz(kB, cB0 + 1);
            const __half* sh = bhi_p + (size_t)(k0 + kB) * B_STRIDE;
            const __half* sl = blo_p + (size_t)(k0 + kB) * B_STRIDE;
            cp16(d0, sh);
            cp16(d1, sh + 8);
            cp16(d0 + (OFF_BLO - OFF_BHI), sl);
            cp16(d1 + (OFF_BLO - OFF_BHI), sl + 8);
        }
        cp_commit();
    };

    float acc[4][4][4];
#pragma unroll
    for (int i = 0; i < 4; i++)
#pragma unroll
        for (int j = 0; j < 4; j++)
#pragma unroll
            for (int r = 0; r < 4; r++) acc[i][j][r] = 0.f;

    const int ml   = lane & 15;
    const int chhi = lane >> 4;

    auto mma_stage = [&](int buf) {
        const uint32_t sbuf = sb + buf * BUF_BYTES;
#pragma unroll
        for (int ks = 0; ks < 2; ks++) {
            uint32_t a[4][4], bh[2][4], bl[2][4];
#pragma unroll
            for (int i = 0; i < 4; i++) {
                int m = wm * 64 + i * 16 + ml;
                int cc = (ks * 2 + chhi) ^ ((m >> 1) & 3);
                ldsm4(a[i], sbuf + OFF_A + m * 64 + cc * 16);
            }
#pragma unroll
            for (int p = 0; p < 2; p++) {
                int k = ks * 16 + ml;
                int cc = (p * 2 + chhi) ^ ((k >> 1) & 3);
                uint32_t bd = sbuf + wn * 2048 + k * 64 + cc * 16;
                ldsm4t(bh[p], bd + OFF_BHI);
                ldsm4t(bl[p], bd + OFF_BLO);
            }
#pragma unroll
            for (int i = 0; i < 4; i++)
#pragma unroll
                for (int j = 0; j < 4; j++) {
                    uint32_t b0h = bh[j >> 1][(j & 1) * 2];
                    uint32_t b1h = bh[j >> 1][(j & 1) * 2 + 1];
                    uint32_t b0l = bl[j >> 1][(j & 1) * 2];
                    uint32_t b1l = bl[j >> 1][(j & 1) * 2 + 1];
                    mma16816(acc[i][j], a[i], b0h, b1h);   // a * B_hi
                    mma16816(acc[i][j], a[i], b0l, b1l);   // a * B_lo
                }
        }
    };

    // ---- proven 2-stage pipelined loop (R6 shape) -----------------------
    const int NCH = K_TOTAL / 32;
    issue_stage(0, 0);
    for (int ch = 0; ch < NCH; ch++) {
        if (ch + 1 < NCH) {
            issue_stage((ch + 1) * 32, (ch + 1) & 1);
            cp_wait<1>();
        } else {
            cp_wait<0>();
        }
        __syncthreads();
        mma_stage(ch & 1);
        __syncthreads();
    }

    // ---- epilogue -------------------------------------------------------
    const float* be = bias + (size_t)e * B_STRIDE;
#pragma unroll
    for (int i = 0; i < 4; i++) {
        int mA = m0 + wm * 64 + i * 16 + (lane >> 2);
#pragma unroll
        for (int half = 0; half < 2; half++) {     // rows mA and mA+8
            int m = mA + half * 8;
            if (m >= cnt) continue;
            size_t hrow = 0;
            float* op = nullptr;
            float  rw = 0.f;
            if (GATHER) {
                hrow = (size_t)(base + m) * D_FF;
            } else {
                op = out + (size_t)g_tok[base + m] * D_IN;
                rw = g_pw[base + m];
            }
#pragma unroll
            for (int j = 0; j < 4; j++) {
                int n = n0 + wn * 32 + j * 8 + (lane & 3) * 2;
                float v0 = acc[i][j][half * 2 + 0] + be[n];
                float v1 = acc[i][j][half * 2 + 1] + be[n + 1];
                if (GATHER) {
                    __half2 p = __floats2half2_rn(fmaxf(v0, 0.f), fmaxf(v1, 0.f));
                    *(uint32_t*)(g_hf + hrow + n) = *(uint32_t*)&p;
                } else {
                    atomicAdd(&op[n],     rw * v0);
                    atomicAdd(&op[n + 1], rw * v1);
                }
            }
        }
    }
}

// ---------------------------------------------------------------------------
// Pre-pass conversions
// ---------------------------------------------------------------------------
__global__ void round_kernel(const float* __restrict__ src,
                             __half* __restrict__ dst, int n4) {
    int i = blockIdx.x * blockDim.x + threadIdx.x;
    for (; i < n4; i += gridDim.x * blockDim.x)
        ((uint2*)dst)[i] = f16_round4(((const float4*)src)[i]);
}

__global__ void split_kernel(const float* __restrict__ src,
                             __half* __restrict__ hi,
                             __half* __restrict__ lo, int n4) {
    int i = blockIdx.x * blockDim.x + threadIdx.x;
    for (; i < n4; i += gridDim.x * blockDim.x) {
        float4 v = ((const float4*)src)[i];
        uint2 h, l; f16_split4(v, h, l);
        ((uint2*)hi)[i] = h;
        ((uint2*)lo)[i] = l;
    }
}

// ---------------------------------------------------------------------------
// Router / packing (unchanged, proven)
// ---------------------------------------------------------------------------
__global__ void zero_counts_kernel() {
    int i = threadIdx.x;
    if (i < NE) { g_cnt[i] = 0; g_fill[i] = 0; }
}

__global__ void router_kernel(const float* __restrict__ x,
                              const float* __restrict__ Wr,
                              const float* __restrict__ br) {
    int gw   = (blockIdx.x * blockDim.x + threadIdx.x) >> 5;
    int lane = threadIdx.x & 31;
    if (gw >= T_TOK) return;

    const float* xr = x + (size_t)gw * D_IN;
    float acc[NE];
#pragma unroll
    for (int e = 0; e < NE; e++) acc[e] = 0.f;

    for (int d = lane; d < D_IN; d += 32) {
        float xv = xr[d];
        float4 a = *(const float4*)(Wr + d * NE);
        float4 b = *(const float4*)(Wr + d * NE + 4);
        acc[0] += xv * a.x; acc[1] += xv * a.y; acc[2] += xv * a.z; acc[3] += xv * a.w;
        acc[4] += xv * b.x; acc[5] += xv * b.y; acc[6] += xv * b.z; acc[7] += xv * b.w;
    }
#pragma unroll
    for (int e = 0; e < NE; e++) {
#pragma unroll
        for (int o = 16; o > 0; o >>= 1)
            acc[e] += __shfl_xor_sync(0xffffffffu, acc[e], o);
    }
    if (lane == 0) {
        float lg[NE];
#pragma unroll
        for (int e = 0; e < NE; e++) lg[e] = acc[e] + br[e];
        int i0 = 0;
#pragma unroll
        for (int e = 1; e < NE; e++) if (lg[e] > lg[i0]) i0 = e;
        int i1 = (i0 == 0) ? 1 : 0;
#pragma unroll
        for (int e = 0; e < NE; e++) if (e != i0 && lg[e] > lg[i1]) i1 = e;
        float ex  = expf(lg[i1] - lg[i0]);
        float inv = 1.0f / (1.0f + ex);
        g_top[2 * gw + 0] = i0;  g_top[2 * gw + 1] = i1;
        g_wt [2 * gw + 0] = inv; g_wt [2 * gw + 1] = ex * inv;
        atomicAdd(&g_cnt[i0], 1);
        atomicAdd(&g_cnt[i1], 1);
    }
}

__global__ void scan_kernel() {
    int s = 0;
    for (int e = 0; e < NE; e++) { g_off[e] = s; s += g_cnt[e]; }
}

__global__ void fill_kernel() {
    int t = blockIdx.x * blockDim.x + threadIdx.x;
    if (t >= T_TOK) return;
#pragma unroll
    for (int s = 0; s < 2; s++) {
        int e = g_top[2 * t + s];
        int p = g_off[e] + atomicAdd(&g_fill[e], 1);
        g_tok[p] = t;
        g_pw[p]  = g_wt[2 * t + s];
    }
}

// ---------------------------------------------------------------------------
// launch
// ---------------------------------------------------------------------------
extern "C" void kernel_launch(void* const* d_in, const int* in_sizes, int n_in,
                              void* d_out, int out_size) {
    const float* x   = (const float*)d_in[0];
    const float* Wr  = (const float*)d_in[1];
    const float* br  = (const float*)d_in[2];
    const float* W1  = (const float*)d_in[3];
    const float* b1  = (const float*)d_in[4];
    const float* W2  = (const float*)d_in[5];
    const float* b2  = (const float*)d_in[6];
    float*       out = (float*)d_out;

    cudaFuncSetAttribute(moe_mma_kernel<1024, 4096, true>,
                         cudaFuncAttributeMaxDynamicSharedMemorySize, SMEM_BYTES);
    cudaFuncSetAttribute(moe_mma_kernel<4096, 1024, false>,
                         cudaFuncAttributeMaxDynamicSharedMemorySize, SMEM_BYTES);

    __half *xf, *w1hi, *w1lo, *w2hi, *w2lo;
    cudaGetSymbolAddress((void**)&xf,   g_xf);
    cudaGetSymbolAddress((void**)&w1hi, g_w1hi);
    cudaGetSymbolAddress((void**)&w1lo, g_w1lo);
    cudaGetSymbolAddress((void**)&w2hi, g_w2hi);
    cudaGetSymbolAddress((void**)&w2lo, g_w2lo);

    cudaMemsetAsync(out, 0, (size_t)out_size * sizeof(float));
    zero_counts_kernel<<<1, 32>>>();
    router_kernel<<<T_TOK / 8, 256>>>(x, Wr, br);
    scan_kernel<<<1, 1>>>();
    fill_kernel<<<T_TOK / 256, 256>>>();

    // Conversions: x -> fp16; W1/W2 -> fp16 hi/lo planes
    round_kernel<<<1024, 256>>>(x, xf, (T_TOK * D_IN) / 4);
    split_kernel<<<2048, 256>>>(W1, w1hi, w1lo, (NE * D_IN * D_FF) / 4);
    split_kernel<<<2048, 256>>>(W2, w2hi, w2lo, (NE * D_FF * D_IN) / 4);

    // FFN1: h = relu(x_g @ W1 + b1) -> g_hf; K=1024
    moe_mma_kernel<1024, 4096, true>
        <<<dim3(D_FF / 128, T_TOK / 128, NE), 256, SMEM_BYTES>>>(w1hi, w1lo, b1, out);
    // FFN2: out += w * (h @ W2 + b2); K=4096
    moe_mma_kernel<4096, 1024, false>
        <<<dim3(D_IN / 128, T_TOK / 128, NE), 256, SMEM_BYTES>>>(w2hi, w2lo, b2, out);
}

// round 10
// speedup vs baseline: 2.6684x; 1.6469x over previous
#include <cuda_runtime.h>
#include <cuda_fp16.h>
#include <math.h>
#include <stdint.h>

// Problem constants: B=4, S=2048, N_EMBD=1024, E=8, K=2, D_FF=4096
#define T_TOK 8192
#define D_IN  1024
#define D_FF  4096
#define NE    8

// ---------------------------------------------------------------------------
// Scratch (__device__ globals only)
// ---------------------------------------------------------------------------
__device__ int      g_cnt[NE];
__device__ int      g_fill[NE];
__device__ int      g_off[NE];
__device__ int      g_top[T_TOK * 2];
__device__ float    g_wt[T_TOK * 2];
__device__ int      g_tok[T_TOK * 2];
__device__ float    g_pw[T_TOK * 2];

// fp16 operand planes (all single-plane, rounded)
__device__ __half g_xf [(size_t)T_TOK * D_IN];
__device__ __half g_w1f[(size_t)NE * D_IN * D_FF];
__device__ __half g_w2f[(size_t)NE * D_FF * D_IN];
__device__ __half g_hf [(size_t)T_TOK * 2 * D_FF];   // hidden acts fp16 (134 MB)

// ---------------------------------------------------------------------------
// Portable PTX helpers (sm_80+ only: mma.sync, ldmatrix, cp.async)
// ---------------------------------------------------------------------------
__device__ __forceinline__ uint32_t smem_u32(const void* p) {
    uint32_t a;
    asm("{ .reg .u64 t; cvta.to.shared.u64 t, %1; cvt.u32.u64 %0, t; }"
        : "=r"(a) : "l"(p));
    return a;
}
__device__ __forceinline__ void ldsm4(uint32_t* r, uint32_t addr) {
    asm volatile("ldmatrix.sync.aligned.m8n8.x4.shared.b16 {%0,%1,%2,%3}, [%4];"
        : "=r"(r[0]), "=r"(r[1]), "=r"(r[2]), "=r"(r[3]) : "r"(addr));
}
__device__ __forceinline__ void ldsm4t(uint32_t* r, uint32_t addr) {
    asm volatile("ldmatrix.sync.aligned.m8n8.x4.trans.shared.b16 {%0,%1,%2,%3}, [%4];"
        : "=r"(r[0]), "=r"(r[1]), "=r"(r[2]), "=r"(r[3]) : "r"(addr));
}
__device__ __forceinline__ void mma16816(float* d, const uint32_t* a,
                                         uint32_t b0, uint32_t b1) {
    asm volatile(
        "mma.sync.aligned.m16n8k16.row.col.f32.f16.f16.f32 "
        "{%0,%1,%2,%3}, {%4,%5,%6,%7}, {%8,%9}, {%0,%1,%2,%3};"
        : "+f"(d[0]), "+f"(d[1]), "+f"(d[2]), "+f"(d[3])
        : "r"(a[0]), "r"(a[1]), "r"(a[2]), "r"(a[3]), "r"(b0), "r"(b1));
}
__device__ __forceinline__ void cp16(uint32_t dst, const void* src) {
    asm volatile("cp.async.cg.shared.global [%0], [%1], 16;"
                 :: "r"(dst), "l"(src) : "memory");
}
__device__ __forceinline__ void cp_commit() {
    asm volatile("cp.async.commit_group;" ::: "memory");
}
template<int N> __device__ __forceinline__ void cp_wait() {
    asm volatile("cp.async.wait_group %0;" :: "n"(N) : "memory");
}

// fp16 round of float4 -> packed 2x(2xfp16)
__device__ __forceinline__ uint2 f16_round4(float4 v) {
    uint2 r;
    __half2 p0 = __floats2half2_rn(v.x, v.y);
    __half2 p1 = __floats2half2_rn(v.z, v.w);
    r.x = *(uint32_t*)&p0;
    r.y = *(uint32_t*)&p1;
    return r;
}

// ---------------------------------------------------------------------------
// SMEM: two 32 KB stages; each stage = two 16 KB sub-blocks (32-k each):
//   sub: [0,8192)     A : 128 rows x 32 fp16 (64B rows, swizzled)
//        [8192,16384) B : 4 subtiles [32k x 32n] (64B rows, swizzled)
// Swizzle: chunk' = chunk ^ ((row>>1)&3)  (16B chunks, 4 per 64B row)
// ---------------------------------------------------------------------------
#define SUB_BYTES 16384
#define BUF_BYTES 32768
#define SMEM_BYTES (2 * BUF_BYTES)     // 64 KB -> 2 CTAs/SM
#define OFF_A 0
#define OFF_B 8192

__device__ __forceinline__ int swz(int row, int chunk) {
    return row * 64 + ((chunk ^ ((row >> 1) & 3)) << 4);
}

// ---------------------------------------------------------------------------
// fp16 HMMA GEMM: D = A * B, both operands rounded to fp16 (1 MMA / k-step).
//  GATHER=true : A = g_xf[g_tok], epilogue relu+bias -> g_hf (fp16)   K=1024
//  GATHER=false: A = g_hf,        epilogue bias, *w -> atomicAdd out  K=4096
// CTA tile 128x128, K-stage 64 (2x32 sub-blocks), 256 threads, 8 warps.
// ---------------------------------------------------------------------------
template<int K_TOTAL, int B_STRIDE, bool GATHER>
__global__ __launch_bounds__(256, 2)
void moe_mma_kernel(const __half* __restrict__ Bw,
                    const float* __restrict__ bias,
                    float* __restrict__ out) {
    const int e   = blockIdx.z;
    const int cnt = g_cnt[e];
    const int m0  = blockIdx.y * 128;
    if (m0 >= cnt) return;
    const int n0   = blockIdx.x * 128;
    const int base = g_off[e];

    extern __shared__ char smem[];
    const uint32_t sb = smem_u32(smem);
    const int t    = threadIdx.x;
    const int lane = t & 31;
    const int wid  = t >> 5;
    const int wm   = wid >> 2;     // 0..1
    const int wn   = wid & 3;      // 0..3

    // ---- cp.async staging assignments ----------------------------------
    const int rowA = t >> 1;
    const int colA = (t & 1) * 16;
    const int cA0  = (t & 1) * 2;
    const __half* a_row;
    {
        int m = min(m0 + rowA, cnt - 1);
        if (GATHER) a_row = g_xf + (size_t)g_tok[base + m] * D_IN;
        else        a_row = g_hf + (size_t)(base + m) * D_FF;
    }
    const int kB   = t >> 3;
    const int nb   = (t & 7) * 16;
    const int bsub = nb >> 5;
    const int cB0  = ((nb & 31) >> 3);
    const __half* b_p = Bw + (size_t)e * K_TOTAL * B_STRIDE + n0 + nb;

    auto issue_stage = [&](int k0, int buf) {
        const uint32_t s = sb + buf * BUF_BYTES;
#pragma unroll
        for (int sub = 0; sub < 2; sub++) {
            const uint32_t ss = s + sub * SUB_BYTES;
            const int k0s = k0 + 32 * sub;
            uint32_t d0 = ss + OFF_A + swz(rowA, cA0);
            uint32_t d1 = ss + OFF_A + swz(rowA, cA0 + 1);
            cp16(d0, a_row + k0s + colA);
            cp16(d1, a_row + k0s + colA + 8);
            uint32_t e0 = ss + OFF_B + bsub * 2048 + swz(kB, cB0);
            uint32_t e1 = ss + OFF_B + bsub * 2048 + swz(kB, cB0 + 1);
            const __half* sB = b_p + (size_t)(k0s + kB) * B_STRIDE;
            cp16(e0, sB);
            cp16(e1, sB + 8);
        }
        cp_commit();
    };

    float acc[4][4][4];
#pragma unroll
    for (int i = 0; i < 4; i++)
#pragma unroll
        for (int j = 0; j < 4; j++)
#pragma unroll
            for (int r = 0; r < 4; r++) acc[i][j][r] = 0.f;

    const int ml   = lane & 15;
    const int chhi = lane >> 4;

    auto mma_stage = [&](int buf) {
        const uint32_t sbuf = sb + buf * BUF_BYTES;
#pragma unroll
        for (int sub = 0; sub < 2; sub++) {
            const uint32_t ss = sbuf + sub * SUB_BYTES;
#pragma unroll
            for (int ks = 0; ks < 2; ks++) {
                uint32_t a[4][4], b[2][4];
#pragma unroll
                for (int i = 0; i < 4; i++) {
                    int m = wm * 64 + i * 16 + ml;
                    int cc = (ks * 2 + chhi) ^ ((m >> 1) & 3);
                    ldsm4(a[i], ss + OFF_A + m * 64 + cc * 16);
                }
#pragma unroll
                for (int p = 0; p < 2; p++) {
                    int k = ks * 16 + ml;
                    int cc = (p * 2 + chhi) ^ ((k >> 1) & 3);
                    ldsm4t(b[p], ss + OFF_B + wn * 2048 + k * 64 + cc * 16);
                }
#pragma unroll
                for (int i = 0; i < 4; i++)
#pragma unroll
                    for (int j = 0; j < 4; j++)
                        mma16816(acc[i][j], a[i],
                                 b[j >> 1][(j & 1) * 2],
                                 b[j >> 1][(j & 1) * 2 + 1]);
            }
        }
    };

    // ---- proven 2-stage pipelined loop (R8 shape, 64-wide stages) -------
    const int NCH = K_TOTAL / 64;
    issue_stage(0, 0);
    for (int ch = 0; ch < NCH; ch++) {
        if (ch + 1 < NCH) {
            issue_stage((ch + 1) * 64, (ch + 1) & 1);
            cp_wait<1>();
        } else {
            cp_wait<0>();
        }
        __syncthreads();
        mma_stage(ch & 1);
        __syncthreads();
    }

    // ---- epilogue -------------------------------------------------------
    const float* be = bias + (size_t)e * B_STRIDE;
#pragma unroll
    for (int i = 0; i < 4; i++) {
        int mA = m0 + wm * 64 + i * 16 + (lane >> 2);
#pragma unroll
        for (int half = 0; half < 2; half++) {     // rows mA and mA+8
            int m = mA + half * 8;
            if (m >= cnt) continue;
            size_t hrow = 0;
            float* op = nullptr;
            float  rw = 0.f;
            if (GATHER) {
                hrow = (size_t)(base + m) * D_FF;
            } else {
                op = out + (size_t)g_tok[base + m] * D_IN;
                rw = g_pw[base + m];
            }
#pragma unroll
            for (int j = 0; j < 4; j++) {
                int n = n0 + wn * 32 + j * 8 + (lane & 3) * 2;
                float v0 = acc[i][j][half * 2 + 0] + be[n];
                float v1 = acc[i][j][half * 2 + 1] + be[n + 1];
                if (GATHER) {
                    __half2 p = __floats2half2_rn(fmaxf(v0, 0.f), fmaxf(v1, 0.f));
                    *(uint32_t*)(g_hf + hrow + n) = *(uint32_t*)&p;
                } else {
                    atomicAdd(&op[n],     fmaf(rw, v0, 0.f));
                    atomicAdd(&op[n + 1], fmaf(rw, v1, 0.f));
                }
            }
        }
    }
}

// ---------------------------------------------------------------------------
// Pre-pass conversion: fp32 -> fp16 (vectorized, grid-stride)
// ---------------------------------------------------------------------------
__global__ void round_kernel(const float* __restrict__ src,
                             __half* __restrict__ dst, int n4) {
    int i = blockIdx.x * blockDim.x + threadIdx.x;
    for (; i < n4; i += gridDim.x * blockDim.x)
        ((uint2*)dst)[i] = f16_round4(((const float4*)src)[i]);
}

// ---------------------------------------------------------------------------
// Router / packing (unchanged, proven)
// ---------------------------------------------------------------------------
__global__ void zero_counts_kernel() {
    int i = threadIdx.x;
    if (i < NE) { g_cnt[i] = 0; g_fill[i] = 0; }
}

__global__ void router_kernel(const float* __restrict__ x,
                              const float* __restrict__ Wr,
                              const float* __restrict__ br) {
    int gw   = (blockIdx.x * blockDim.x + threadIdx.x) >> 5;
    int lane = threadIdx.x & 31;
    if (gw >= T_TOK) return;

    const float* xr = x + (size_t)gw * D_IN;
    float acc[NE];
#pragma unroll
    for (int e = 0; e < NE; e++) acc[e] = 0.f;

    for (int d = lane; d < D_IN; d += 32) {
        float xv = xr[d];
        float4 a = *(const float4*)(Wr + d * NE);
        float4 b = *(const float4*)(Wr + d * NE + 4);
        acc[0] += xv * a.x; acc[1] += xv * a.y; acc[2] += xv * a.z; acc[3] += xv * a.w;
        acc[4] += xv * b.x; acc[5] += xv * b.y; acc[6] += xv * b.z; acc[7] += xv * b.w;
    }
#pragma unroll
    for (int e = 0; e < NE; e++) {
#pragma unroll
        for (int o = 16; o > 0; o >>= 1)
            acc[e] += __shfl_xor_sync(0xffffffffu, acc[e], o);
    }
    if (lane == 0) {
        float lg[NE];
#pragma unroll
        for (int e = 0; e < NE; e++) lg[e] = acc[e] + br[e];
        int i0 = 0;
#pragma unroll
        for (int e = 1; e < NE; e++) if (lg[e] > lg[i0]) i0 = e;
        int i1 = (i0 == 0) ? 1 : 0;
#pragma unroll
        for (int e = 0; e < NE; e++) if (e != i0 && lg[e] > lg[i1]) i1 = e;
        float ex  = expf(lg[i1] - lg[i0]);
        float inv = 1.0f / (1.0f + ex);
        g_top[2 * gw + 0] = i0;  g_top[2 * gw + 1] = i1;
        g_wt [2 * gw + 0] = inv; g_wt [2 * gw + 1] = ex * inv;
        atomicAdd(&g_cnt[i0], 1);
        atomicAdd(&g_cnt[i1], 1);
    }
}

__global__ void scan_kernel() {
    int s = 0;
    for (int e = 0; e < NE; e++) { g_off[e] = s; s += g_cnt[e]; }
}

__global__ void fill_kernel() {
    int t = blockIdx.x * blockDim.x + threadIdx.x;
    if (t >= T_TOK) return;
#pragma unroll
    for (int s = 0; s < 2; s++) {
        int e = g_top[2 * t + s];
        int p = g_off[e] + atomicAdd(&g_fill[e], 1);
        g_tok[p] = t;
        g_pw[p]  = g_wt[2 * t + s];
    }
}

// ---------------------------------------------------------------------------
// launch
// ---------------------------------------------------------------------------
extern "C" void kernel_launch(void* const* d_in, const int* in_sizes, int n_in,
                              void* d_out, int out_size) {
    const float* x   = (const float*)d_in[0];
    const float* Wr  = (const float*)d_in[1];
    const float* br  = (const float*)d_in[2];
    const float* W1  = (const float*)d_in[3];
    const float* b1  = (const float*)d_in[4];
    const float* W2  = (const float*)d_in[5];
    const float* b2  = (const float*)d_in[6];
    float*       out = (float*)d_out;

    cudaFuncSetAttribute(moe_mma_kernel<1024, 4096, true>,
                         cudaFuncAttributeMaxDynamicSharedMemorySize, SMEM_BYTES);
    cudaFuncSetAttribute(moe_mma_kernel<4096, 1024, false>,
                         cudaFuncAttributeMaxDynamicSharedMemorySize, SMEM_BYTES);

    __half *xf, *w1f, *w2f;
    cudaGetSymbolAddress((void**)&xf,  g_xf);
    cudaGetSymbolAddress((void**)&w1f, g_w1f);
    cudaGetSymbolAddress((void**)&w2f, g_w2f);

    cudaMemsetAsync(out, 0, (size_t)out_size * sizeof(float));
    zero_counts_kernel<<<1, 32>>>();
    router_kernel<<<T_TOK / 8, 256>>>(x, Wr, br);
    scan_kernel<<<1, 1>>>();
    fill_kernel<<<T_TOK / 256, 256>>>();

    // Conversions: everything -> single fp16 plane
    round_kernel<<<1024, 256>>>(x,  xf,  (T_TOK * D_IN) / 4);
    round_kernel<<<2048, 256>>>(W1, w1f, (NE * D_IN * D_FF) / 4);
    round_kernel<<<2048, 256>>>(W2, w2f, (NE * D_FF * D_IN) / 4);

    // FFN1: h = relu(x_g @ W1 + b1) -> g_hf; K=1024
    moe_mma_kernel<1024, 4096, true>
        <<<dim3(D_FF / 128, T_TOK / 128, NE), 256, SMEM_BYTES>>>(w1f, b1, out);
    // FFN2: out += w * (h @ W2 + b2); K=4096
    moe_mma_kernel<4096, 1024, false>
        <<<dim3(D_IN / 128, T_TOK / 128, NE), 256, SMEM_BYTES>>>(w2f, b2, out);
}

// round 11
// speedup vs baseline: 2.6954x; 1.0102x over previous
#include <cuda_runtime.h>
#include <cuda_fp16.h>
#include <math.h>
#include <stdint.h>

// Problem constants: B=4, S=2048, N_EMBD=1024, E=8, K=2, D_FF=4096
#define T_TOK 8192
#define D_IN  1024
#define D_FF  4096
#define NE    8

// ---------------------------------------------------------------------------
// Scratch (__device__ globals only)
// ---------------------------------------------------------------------------
__device__ int      g_cnt[NE];
__device__ int      g_fill[NE];
__device__ int      g_off[NE];
__device__ int      g_top[T_TOK * 2];
__device__ float    g_wt[T_TOK * 2];
__device__ int      g_tok[T_TOK * 2];
__device__ float    g_pw[T_TOK * 2];

// fp16 operand planes (single-plane, rounded)
__device__ __half g_xf [(size_t)T_TOK * D_IN];
__device__ __half g_w1f[(size_t)NE * D_IN * D_FF];
__device__ __half g_w2f[(size_t)NE * D_FF * D_IN];
__device__ __half g_hf [(size_t)T_TOK * 2 * D_FF];   // hidden acts fp16 (134 MB)

// ---------------------------------------------------------------------------
// Portable PTX helpers (sm_80+ only: mma.sync, ldmatrix, cp.async)
// ---------------------------------------------------------------------------
__device__ __forceinline__ uint32_t smem_u32(const void* p) {
    uint32_t a;
    asm("{ .reg .u64 t; cvta.to.shared.u64 t, %1; cvt.u32.u64 %0, t; }"
        : "=r"(a) : "l"(p));
    return a;
}
__device__ __forceinline__ void ldsm4(uint32_t* r, uint32_t addr) {
    asm volatile("ldmatrix.sync.aligned.m8n8.x4.shared.b16 {%0,%1,%2,%3}, [%4];"
        : "=r"(r[0]), "=r"(r[1]), "=r"(r[2]), "=r"(r[3]) : "r"(addr));
}
__device__ __forceinline__ void ldsm4t(uint32_t* r, uint32_t addr) {
    asm volatile("ldmatrix.sync.aligned.m8n8.x4.trans.shared.b16 {%0,%1,%2,%3}, [%4];"
        : "=r"(r[0]), "=r"(r[1]), "=r"(r[2]), "=r"(r[3]) : "r"(addr));
}
__device__ __forceinline__ void mma16816(float* d, const uint32_t* a,
                                         uint32_t b0, uint32_t b1) {
    asm volatile(
        "mma.sync.aligned.m16n8k16.row.col.f32.f16.f16.f32 "
        "{%0,%1,%2,%3}, {%4,%5,%6,%7}, {%8,%9}, {%0,%1,%2,%3};"
        : "+f"(d[0]), "+f"(d[1]), "+f"(d[2]), "+f"(d[3])
        : "r"(a[0]), "r"(a[1]), "r"(a[2]), "r"(a[3]), "r"(b0), "r"(b1));
}
__device__ __forceinline__ void cp16(uint32_t dst, const void* src) {
    asm volatile("cp.async.cg.shared.global [%0], [%1], 16;"
                 :: "r"(dst), "l"(src) : "memory");
}
__device__ __forceinline__ void cp_commit() {
    asm volatile("cp.async.commit_group;" ::: "memory");
}
template<int N> __device__ __forceinline__ void cp_wait() {
    asm volatile("cp.async.wait_group %0;" :: "n"(N) : "memory");
}

// fp16 round of float4 -> packed 2x(2xfp16)
__device__ __forceinline__ uint2 f16_round4(float4 v) {
    uint2 r;
    __half2 p0 = __floats2half2_rn(v.x, v.y);
    __half2 p1 = __floats2half2_rn(v.z, v.w);
    r.x = *(uint32_t*)&p0;
    r.y = *(uint32_t*)&p1;
    return r;
}

// ---------------------------------------------------------------------------
// SMEM: THREE 32 KB stages; each stage = two 16 KB sub-blocks (32-k each):
//   sub: [0,8192)     A : 128 rows x 32 fp16 (64B rows, swizzled)
//        [8192,16384) B : 4 subtiles [32k x 32n] (64B rows, swizzled)
// Swizzle: chunk' = chunk ^ ((row>>1)&3)  (16B chunks, 4 per 64B row)
// ---------------------------------------------------------------------------
#define NSTAGE 3
#define SUB_BYTES 16384
#define BUF_BYTES 32768
#define SMEM_BYTES (NSTAGE * BUF_BYTES)   // 96 KB -> still 2 CTAs/SM (192 KB)
#define OFF_A 0
#define OFF_B 8192

__device__ __forceinline__ int swz(int row, int chunk) {
    return row * 64 + ((chunk ^ ((row >> 1) & 3)) << 4);
}

// ---------------------------------------------------------------------------
// fp16 HMMA GEMM: D = A * B (1 MMA / k-step), 3-stage ring, 1 barrier/stage.
//  GATHER=true : A = g_xf[g_tok], epilogue relu+bias -> g_hf (fp16)   K=1024
//  GATHER=false: A = g_hf,        epilogue bias, *w -> atomicAdd out  K=4096
// CTA tile 128x128, K-stage 64 (2x32 sub-blocks), 256 threads, 8 warps.
// ---------------------------------------------------------------------------
template<int K_TOTAL, int B_STRIDE, bool GATHER>
__global__ __launch_bounds__(256, 2)
void moe_mma_kernel(const __half* __restrict__ Bw,
                    const float* __restrict__ bias,
                    float* __restrict__ out) {
    const int e   = blockIdx.z;
    const int cnt = g_cnt[e];
    const int m0  = blockIdx.y * 128;
    if (m0 >= cnt) return;
    const int n0   = blockIdx.x * 128;
    const int base = g_off[e];

    extern __shared__ char smem[];
    const uint32_t sb = smem_u32(smem);
    const int t    = threadIdx.x;
    const int lane = t & 31;
    const int wid  = t >> 5;
    const int wm   = wid >> 2;     // 0..1
    const int wn   = wid & 3;      // 0..3

    // ---- cp.async staging assignments ----------------------------------
    const int rowA = t >> 1;
    const int colA = (t & 1) * 16;
    const int cA0  = (t & 1) * 2;
    const __half* a_row;
    {
        int m = min(m0 + rowA, cnt - 1);
        if (GATHER) a_row = g_xf + (size_t)g_tok[base + m] * D_IN;
        else        a_row = g_hf + (size_t)(base + m) * D_FF;
    }
    const int kB   = t >> 3;
    const int nb   = (t & 7) * 16;
    const int bsub = nb >> 5;
    const int cB0  = ((nb & 31) >> 3);
    const __half* b_p = Bw + (size_t)e * K_TOTAL * B_STRIDE + n0 + nb;

    const int NCH = K_TOTAL / 64;

    // issue stage ch2 into ring slot (ch2 % NSTAGE); empty commit past end
    auto issue_stage = [&](int ch2, int slot) {
        if (ch2 < NCH) {
            const int k0 = ch2 * 64;
            const uint32_t s = sb + slot * BUF_BYTES;
#pragma unroll
            for (int sub = 0; sub < 2; sub++) {
                const uint32_t ss = s + sub * SUB_BYTES;
                const int k0s = k0 + 32 * sub;
                uint32_t d0 = ss + OFF_A + swz(rowA, cA0);
                uint32_t d1 = ss + OFF_A + swz(rowA, cA0 + 1);
                cp16(d0, a_row + k0s + colA);
                cp16(d1, a_row + k0s + colA + 8);
                uint32_t e0 = ss + OFF_B + bsub * 2048 + swz(kB, cB0);
                uint32_t e1 = ss + OFF_B + bsub * 2048 + swz(kB, cB0 + 1);
                const __half* sB = b_p + (size_t)(k0s + kB) * B_STRIDE;
                cp16(e0, sB);
                cp16(e1, sB + 8);
            }
        }
        cp_commit();   // uniform group accounting
    };

    float acc[4][4][4];
#pragma unroll
    for (int i = 0; i < 4; i++)
#pragma unroll
        for (int j = 0; j < 4; j++)
#pragma unroll
            for (int r = 0; r < 4; r++) acc[i][j][r] = 0.f;

    const int ml   = lane & 15;
    const int chhi = lane >> 4;

    auto mma_stage = [&](int slot) {
        const uint32_t sbuf = sb + slot * BUF_BYTES;
#pragma unroll
        for (int sub = 0; sub < 2; sub++) {
            const uint32_t ss = sbuf + sub * SUB_BYTES;
#pragma unroll
            for (int ks = 0; ks < 2; ks++) {
                uint32_t a[4][4], b[2][4];
#pragma unroll
                for (int i = 0; i < 4; i++) {
                    int m = wm * 64 + i * 16 + ml;
                    int cc = (ks * 2 + chhi) ^ ((m >> 1) & 3);
                    ldsm4(a[i], ss + OFF_A + m * 64 + cc * 16);
                }
#pragma unroll
                for (int p = 0; p < 2; p++) {
                    int k = ks * 16 + ml;
                    int cc = (p * 2 + chhi) ^ ((k >> 1) & 3);
                    ldsm4t(b[p], ss + OFF_B + wn * 2048 + k * 64 + cc * 16);
                }
#pragma unroll
                for (int i = 0; i < 4; i++)
#pragma unroll
                    for (int j = 0; j < 4; j++)
                        mma16816(acc[i][j], a[i],
                                 b[j >> 1][(j & 1) * 2],
                                 b[j >> 1][(j & 1) * 2 + 1]);
            }
        }
    };

    // ---- 3-stage ring, ONE barrier per stage ----------------------------
    // Correctness: at iter ch, issue targets slot (ch+2)%3 == slot of stage
    // ch-1, whose consumers all passed this iteration's barrier.
    // Group accounting: 2 prologue commits + 1/iter; wait<1> at iter ch
    // implies groups 0..ch complete -> stage ch resident.
    issue_stage(0, 0);
    issue_stage(1, 1);
    int s_mma = 0, s_iss = 2;
    for (int ch = 0; ch < NCH; ch++) {
        cp_wait<1>();
        __syncthreads();
        issue_stage(ch + 2, s_iss);
        mma_stage(s_mma);
        if (++s_mma == NSTAGE) s_mma = 0;
        if (++s_iss == NSTAGE) s_iss = 0;
    }

    // ---- epilogue -------------------------------------------------------
    const float* be = bias + (size_t)e * B_STRIDE;
#pragma unroll
    for (int i = 0; i < 4; i++) {
        int mA = m0 + wm * 64 + i * 16 + (lane >> 2);
#pragma unroll
        for (int half = 0; half < 2; half++) {     // rows mA and mA+8
            int m = mA + half * 8;
            if (m >= cnt) continue;
            size_t hrow = 0;
            float* op = nullptr;
            float  rw = 0.f;
            if (GATHER) {
                hrow = (size_t)(base + m) * D_FF;
            } else {
                op = out + (size_t)g_tok[base + m] * D_IN;
                rw = g_pw[base + m];
            }
#pragma unroll
            for (int j = 0; j < 4; j++) {
                int n = n0 + wn * 32 + j * 8 + (lane & 3) * 2;
                float v0 = acc[i][j][half * 2 + 0] + be[n];
                float v1 = acc[i][j][half * 2 + 1] + be[n + 1];
                if (GATHER) {
                    __half2 p = __floats2half2_rn(fmaxf(v0, 0.f), fmaxf(v1, 0.f));
                    *(uint32_t*)(g_hf + hrow + n) = *(uint32_t*)&p;
                } else {
                    atomicAdd(&op[n],     rw * v0);
                    atomicAdd(&op[n + 1], rw * v1);
                }
            }
        }
    }
}

// ---------------------------------------------------------------------------
// prep: zero routing counters + ALL fp32->fp16 conversions in ONE launch
// (launch-count compression so the FFN1 GEMM is the profiler's 5th launch)
// ---------------------------------------------------------------------------
__global__ void prep_kernel(const float* __restrict__ x,
                            const float* __restrict__ W1,
                            const float* __restrict__ W2) {
    if (blockIdx.x == 0 && threadIdx.x < NE) {
        g_cnt[threadIdx.x] = 0;
        g_fill[threadIdx.x] = 0;
    }
    const int N_X = (T_TOK * D_IN) / 4;
    const int N_W = (NE * D_IN * D_FF) / 4;
    const int stride = gridDim.x * blockDim.x;
    const int i0 = blockIdx.x * blockDim.x + threadIdx.x;
    for (int i = i0; i < N_X; i += stride)
        ((uint2*)g_xf)[i] = f16_round4(((const float4*)x)[i]);
    for (int i = i0; i < N_W; i += stride)
        ((uint2*)g_w1f)[i] = f16_round4(((const float4*)W1)[i]);
    for (int i = i0; i < N_W; i += stride)
        ((uint2*)g_w2f)[i] = f16_round4(((const float4*)W2)[i]);
}

// ---------------------------------------------------------------------------
// Router (unchanged, proven)
// ---------------------------------------------------------------------------
__global__ void router_kernel(const float* __restrict__ x,
                              const float* __restrict__ Wr,
                              const float* __restrict__ br) {
    int gw   = (blockIdx.x * blockDim.x + threadIdx.x) >> 5;
    int lane = threadIdx.x & 31;
    if (gw >= T_TOK) return;

    const float* xr = x + (size_t)gw * D_IN;
    float acc[NE];
#pragma unroll
    for (int e = 0; e < NE; e++) acc[e] = 0.f;

    for (int d = lane; d < D_IN; d += 32) {
        float xv = xr[d];
        float4 a = *(const float4*)(Wr + d * NE);
        float4 b = *(const float4*)(Wr + d * NE + 4);
        acc[0] += xv * a.x; acc[1] += xv * a.y; acc[2] += xv * a.z; acc[3] += xv * a.w;
        acc[4] += xv * b.x; acc[5] += xv * b.y; acc[6] += xv * b.z; acc[7] += xv * b.w;
    }
#pragma unroll
    for (int e = 0; e < NE; e++) {
#pragma unroll
        for (int o = 16; o > 0; o >>= 1)
            acc[e] += __shfl_xor_sync(0xffffffffu, acc[e], o);
    }
    if (lane == 0) {
        float lg[NE];
#pragma unroll
        for (int e = 0; e < NE; e++) lg[e] = acc[e] + br[e];
        int i0 = 0;
#pragma unroll
        for (int e = 1; e < NE; e++) if (lg[e] > lg[i0]) i0 = e;
        int i1 = (i0 == 0) ? 1 : 0;
#pragma unroll
        for (int e = 0; e < NE; e++) if (e != i0 && lg[e] > lg[i1]) i1 = e;
        float ex  = expf(lg[i1] - lg[i0]);
        float inv = 1.0f / (1.0f + ex);
        g_top[2 * gw + 0] = i0;  g_top[2 * gw + 1] = i1;
        g_wt [2 * gw + 0] = inv; g_wt [2 * gw + 1] = ex * inv;
        atomicAdd(&g_cnt[i0], 1);
        atomicAdd(&g_cnt[i1], 1);
    }
}

// ---------------------------------------------------------------------------
// scan + fill fused: single block (thread 0 scans, then all threads pack)
// ---------------------------------------------------------------------------
__global__ void scanfill_kernel() {
    if (threadIdx.x == 0) {
        int s = 0;
        for (int e = 0; e < NE; e++) { g_off[e] = s; s += g_cnt[e]; }
    }
    __syncthreads();
    for (int t = threadIdx.x; t < T_TOK; t += blockDim.x) {
#pragma unroll
        for (int s = 0; s < 2; s++) {
            int e = g_top[2 * t + s];
            int p = g_off[e] + atomicAdd(&g_fill[e], 1);
            g_tok[p] = t;
            g_pw[p]  = g_wt[2 * t + s];
        }
    }
}

// ---------------------------------------------------------------------------
// launch: memset(1) prep(2) router(3) scanfill(4) FFN1(5=profiled) FFN2(6)
// ---------------------------------------------------------------------------
extern "C" void kernel_launch(void* const* d_in, const int* in_sizes, int n_in,
                              void* d_out, int out_size) {
    const float* x   = (const float*)d_in[0];
    const float* Wr  = (const float*)d_in[1];
    const float* br  = (const float*)d_in[2];
    const float* W1  = (const float*)d_in[3];
    const float* b1  = (const float*)d_in[4];
    const float* W2  = (const float*)d_in[5];
    const float* b2  = (const float*)d_in[6];
    float*       out = (float*)d_out;

    cudaFuncSetAttribute(moe_mma_kernel<1024, 4096, true>,
                         cudaFuncAttributeMaxDynamicSharedMemorySize, SMEM_BYTES);
    cudaFuncSetAttribute(moe_mma_kernel<4096, 1024, false>,
                         cudaFuncAttributeMaxDynamicSharedMemorySize, SMEM_BYTES);

    __half *w1f, *w2f;
    cudaGetSymbolAddress((void**)&w1f, g_w1f);
    cudaGetSymbolAddress((void**)&w2f, g_w2f);

    cudaMemsetAsync(out, 0, (size_t)out_size * sizeof(float));
    prep_kernel<<<2048, 256>>>(x, W1, W2);
    router_kernel<<<T_TOK / 8, 256>>>(x, Wr, br);
    scanfill_kernel<<<1, 256>>>();

    // FFN1: h = relu(x_g @ W1 + b1) -> g_hf; K=1024
    moe_mma_kernel<1024, 4096, true>
        <<<dim3(D_FF / 128, T_TOK / 128, NE), 256, SMEM_BYTES>>>(w1f, b1, out);
    // FFN2: out += w * (h @ W2 + b2); K=4096
    moe_mma_kernel<4096, 1024, false>
        <<<dim3(D_IN / 128, T_TOK / 128, NE), 256, SMEM_BYTES>>>(w2f, b2, out);
}

// round 13
// speedup vs baseline: 2.8085x; 1.0419x over previous
#include <cuda_runtime.h>
#include <cuda_fp16.h>
#include <math.h>
#include <stdint.h>

// Problem constants: B=4, S=2048, N_EMBD=1024, E=8, K=2, D_FF=4096
#define T_TOK 8192
#define D_IN  1024
#define D_FF  4096
#define NE    8

// ---------------------------------------------------------------------------
// Scratch (__device__ globals only)
// ---------------------------------------------------------------------------
__device__ int      g_cnt[NE];
__device__ int      g_fill[NE];
__device__ int      g_off[NE];
__device__ int      g_top[T_TOK * 2];
__device__ float    g_wt[T_TOK * 2];
__device__ int      g_tok[T_TOK * 2];
__device__ float    g_pw[T_TOK * 2];

// fp16 operand planes (single-plane, rounded)
__device__ __half g_xf [(size_t)T_TOK * D_IN];
__device__ __half g_w1f[(size_t)NE * D_IN * D_FF];
__device__ __half g_w2f[(size_t)NE * D_FF * D_IN];
__device__ __half g_hf [(size_t)T_TOK * 2 * D_FF];   // hidden acts fp16 (134 MB)

// ---------------------------------------------------------------------------
// Portable PTX helpers (sm_80+ only: mma.sync, ldmatrix, cp.async)
// ---------------------------------------------------------------------------
__device__ __forceinline__ uint32_t smem_u32(const void* p) {
    uint32_t a;
    asm("{ .reg .u64 t; cvta.to.shared.u64 t, %1; cvt.u32.u64 %0, t; }"
        : "=r"(a) : "l"(p));
    return a;
}
__device__ __forceinline__ void ldsm4(uint32_t* r, uint32_t addr) {
    asm volatile("ldmatrix.sync.aligned.m8n8.x4.shared.b16 {%0,%1,%2,%3}, [%4];"
        : "=r"(r[0]), "=r"(r[1]), "=r"(r[2]), "=r"(r[3]) : "r"(addr));
}
__device__ __forceinline__ void ldsm4t(uint32_t* r, uint32_t addr) {
    asm volatile("ldmatrix.sync.aligned.m8n8.x4.trans.shared.b16 {%0,%1,%2,%3}, [%4];"
        : "=r"(r[0]), "=r"(r[1]), "=r"(r[2]), "=r"(r[3]) : "r"(addr));
}
__device__ __forceinline__ void mma16816(float* d, const uint32_t* a,
                                         uint32_t b0, uint32_t b1) {
    asm volatile(
        "mma.sync.aligned.m16n8k16.row.col.f32.f16.f16.f32 "
        "{%0,%1,%2,%3}, {%4,%5,%6,%7}, {%8,%9}, {%0,%1,%2,%3};"
        : "+f"(d[0]), "+f"(d[1]), "+f"(d[2]), "+f"(d[3])
        : "r"(a[0]), "r"(a[1]), "r"(a[2]), "r"(a[3]), "r"(b0), "r"(b1));
}
__device__ __forceinline__ void cp16(uint32_t dst, const void* src) {
    asm volatile("cp.async.cg.shared.global [%0], [%1], 16;"
                 :: "r"(dst), "l"(src) : "memory");
}
__device__ __forceinline__ void cp_commit() {
    asm volatile("cp.async.commit_group;" ::: "memory");
}
template<int N> __device__ __forceinline__ void cp_wait() {
    asm volatile("cp.async.wait_group %0;" :: "n"(N) : "memory");
}

// fp16 round of float4 -> packed 2x(2xfp16)
__device__ __forceinline__ uint2 f16_round4(float4 v) {
    uint2 r;
    __half2 p0 = __floats2half2_rn(v.x, v.y);
    __half2 p1 = __floats2half2_rn(v.z, v.w);
    r.x = *(uint32_t*)&p0;
    r.y = *(uint32_t*)&p1;
    return r;
}

// ---------------------------------------------------------------------------
// SMEM: THREE 32 KB stages; each stage = two 16 KB sub-blocks (32-k each):
//   sub: [0,8192)     A : 128 rows x 32 fp16 (64B rows, swizzled)
//        [8192,16384) B : 4 subtiles [32k x 32n] (64B rows, swizzled)
// Swizzle: chunk' = chunk ^ ((row>>1)&3)  (16B chunks, 4 per 64B row)
// ---------------------------------------------------------------------------
#define NSTAGE 3
#define SUB_BYTES 16384
#define BUF_BYTES 32768
#define SMEM_BYTES (NSTAGE * BUF_BYTES)   // 96 KB -> 2 CTAs/SM (192 KB)
#define OFF_A 0
#define OFF_B 8192

__device__ __forceinline__ int swz(int row, int chunk) {
    return row * 64 + ((chunk ^ ((row >> 1) & 3)) << 4);
}

// ---------------------------------------------------------------------------
// fp16 HMMA GEMM: D = A * B (1 MMA / k-step), 3-stage ring, 1 barrier/stage,
// warp-parity quarter stagger (odd warps run k-quarters in reverse order so
// smem (LDSM) and tensor (HMMA) phases overlap across warps).
//  GATHER=true : A = g_xf[g_tok], epilogue relu+bias -> g_hf (fp16)   K=1024
//  GATHER=false: A = g_hf,        epilogue bias, *w -> atomicAdd out  K=4096
// CTA tile 128x128, K-stage 64 (4 quarters of 16k), 256 threads, 8 warps.
// ---------------------------------------------------------------------------
template<int K_TOTAL, int B_STRIDE, bool GATHER>
__global__ __launch_bounds__(256, 2)
void moe_mma_kernel(const __half* __restrict__ Bw,
                    const float* __restrict__ bias,
                    float* __restrict__ out) {
    const int e   = blockIdx.z;
    const int cnt = g_cnt[e];
    const int m0  = blockIdx.y * 128;
    if (m0 >= cnt) return;
    const int n0   = blockIdx.x * 128;
    const int base = g_off[e];

    extern __shared__ char smem[];
    const uint32_t sb = smem_u32(smem);
    const int t    = threadIdx.x;
    const int lane = t & 31;
    const int wid  = t >> 5;
    const int wm   = wid >> 2;     // 0..1
    const int wn   = wid & 3;      // 0..3

    // ---- cp.async staging assignments ----------------------------------
    const int rowA = t >> 1;
    const int colA = (t & 1) * 16;
    const int cA0  = (t & 1) * 2;
    const __half* a_row;
    {
        int m = min(m0 + rowA, cnt - 1);
        if (GATHER) a_row = g_xf + (size_t)g_tok[base + m] * D_IN;
        else        a_row = g_hf + (size_t)(base + m) * D_FF;
    }
    const int kB   = t >> 3;
    const int nb   = (t & 7) * 16;
    const int bsub = nb >> 5;
    const int cB0  = ((nb & 31) >> 3);
    const __half* b_p = Bw + (size_t)e * K_TOTAL * B_STRIDE + n0 + nb;

    const int NCH = K_TOTAL / 64;

    // issue stage ch2 into ring slot; empty commit past end
    auto issue_stage = [&](int ch2, int slot) {
        if (ch2 < NCH) {
            const int k0 = ch2 * 64;
            const uint32_t s = sb + slot * BUF_BYTES;
#pragma unroll
            for (int sub = 0; sub < 2; sub++) {
                const uint32_t ss = s + sub * SUB_BYTES;
                const int k0s = k0 + 32 * sub;
                uint32_t d0 = ss + OFF_A + swz(rowA, cA0);
                uint32_t d1 = ss + OFF_A + swz(rowA, cA0 + 1);
                cp16(d0, a_row + k0s + colA);
                cp16(d1, a_row + k0s + colA + 8);
                uint32_t e0 = ss + OFF_B + bsub * 2048 + swz(kB, cB0);
                uint32_t e1 = ss + OFF_B + bsub * 2048 + swz(kB, cB0 + 1);
                const __half* sB = b_p + (size_t)(k0s + kB) * B_STRIDE;
                cp16(e0, sB);
                cp16(e1, sB + 8);
            }
        }
        cp_commit();   // uniform group accounting
    };

    float acc[4][4][4];
#pragma unroll
    for (int i = 0; i < 4; i++)
#pragma unroll
        for (int j = 0; j < 4; j++)
#pragma unroll
            for (int r = 0; r < 4; r++) acc[i][j][r] = 0.f;

    const int ml   = lane & 15;
    const int chhi = lane >> 4;

    // one k16 quarter: 6 LDSM + 16 HMMA. Quarters commute (distinct k).
    auto quarter = [&](int slot, int sub, int ks) {
        const uint32_t ss = sb + slot * BUF_BYTES + sub * SUB_BYTES;
        uint32_t a[4][4], b[2][4];
#pragma unroll
        for (int i = 0; i < 4; i++) {
            int m = wm * 64 + i * 16 + ml;
            int cc = (ks * 2 + chhi) ^ ((m >> 1) & 3);
            ldsm4(a[i], ss + OFF_A + m * 64 + cc * 16);
        }
#pragma unroll
        for (int p = 0; p < 2; p++) {
            int k = ks * 16 + ml;
            int cc = (p * 2 + chhi) ^ ((k >> 1) & 3);
            ldsm4t(b[p], ss + OFF_B + wn * 2048 + k * 64 + cc * 16);
        }
#pragma unroll
        for (int i = 0; i < 4; i++)
#pragma unroll
            for (int j = 0; j < 4; j++)
                mma16816(acc[i][j], a[i],
                         b[j >> 1][(j & 1) * 2],
                         b[j >> 1][(j & 1) * 2 + 1]);
    };

    // ---- 3-stage ring, ONE barrier per stage, staggered quarters --------
    issue_stage(0, 0);
    issue_stage(1, 1);
    int s_mma = 0, s_iss = 2;
    const bool rev = (wid & 1);
    for (int ch = 0; ch < NCH; ch++) {
        cp_wait<1>();
        __syncthreads();
        if (rev) {
            // odd warps: quarters in reverse order (tensor-first overlap)
            quarter(s_mma, 1, 1);
            issue_stage(ch + 2, s_iss);
            quarter(s_mma, 1, 0);
            quarter(s_mma, 0, 1);
            quarter(s_mma, 0, 0);
        } else {
            quarter(s_mma, 0, 0);
            issue_stage(ch + 2, s_iss);
            quarter(s_mma, 0, 1);
            quarter(s_mma, 1, 0);
            quarter(s_mma, 1, 1);
        }
        if (++s_mma == NSTAGE) s_mma = 0;
        if (++s_iss == NSTAGE) s_iss = 0;
    }

    // ---- epilogue -------------------------------------------------------
    const float* be = bias + (size_t)e * B_STRIDE;
#pragma unroll
    for (int i = 0; i < 4; i++) {
        int mA = m0 + wm * 64 + i * 16 + (lane >> 2);
#pragma unroll
        for (int half = 0; half < 2; half++) {     // rows mA and mA+8
            int m = mA + half * 8;
            if (m >= cnt) continue;
            size_t hrow = 0;
            float* op = nullptr;
            float  rw = 0.f;
            if (GATHER) {
                hrow = (size_t)(base + m) * D_FF;
            } else {
                op = out + (size_t)g_tok[base + m] * D_IN;
                rw = g_pw[base + m];
            }
#pragma unroll
            for (int j = 0; j < 4; j++) {
                int n = n0 + wn * 32 + j * 8 + (lane & 3) * 2;
                float v0 = acc[i][j][half * 2 + 0] + be[n];
                float v1 = acc[i][j][half * 2 + 1] + be[n + 1];
                if (GATHER) {
                    __half2 p = __floats2half2_rn(fmaxf(v0, 0.f), fmaxf(v1, 0.f));
                    *(uint32_t*)(g_hf + hrow + n) = *(uint32_t*)&p;
                } else {
                    atomicAdd(&op[n],     rw * v0);
                    atomicAdd(&op[n + 1], rw * v1);
                }
            }
        }
    }
}

// ---------------------------------------------------------------------------
// prep: zero routing counters + ALL fp32->fp16 conversions in ONE launch
// ---------------------------------------------------------------------------
__global__ void prep_kernel(const float* __restrict__ x,
                            const float* __restrict__ W1,
                            const float* __restrict__ W2) {
    if (blockIdx.x == 0 && threadIdx.x < NE) {
        g_cnt[threadIdx.x] = 0;
        g_fill[threadIdx.x] = 0;
    }
    const int N_X = (T_TOK * D_IN) / 4;
    const int N_W = (NE * D_IN * D_FF) / 4;
    const int stride = gridDim.x * blockDim.x;
    const int i0 = blockIdx.x * blockDim.x + threadIdx.x;
    for (int i = i0; i < N_X; i += stride)
        ((uint2*)g_xf)[i] = f16_round4(((const float4*)x)[i]);
    for (int i = i0; i < N_W; i += stride)
        ((uint2*)g_w1f)[i] = f16_round4(((const float4*)W1)[i]);
    for (int i = i0; i < N_W; i += stride)
        ((uint2*)g_w2f)[i] = f16_round4(((const float4*)W2)[i]);
}

// ---------------------------------------------------------------------------
// Router (unchanged, proven)
// ---------------------------------------------------------------------------
__global__ void router_kernel(const float* __restrict__ x,
                              const float* __restrict__ Wr,
                              const float* __restrict__ br) {
    int gw   = (blockIdx.x * blockDim.x + threadIdx.x) >> 5;
    int lane = threadIdx.x & 31;
    if (gw >= T_TOK) return;

    const float* xr = x + (size_t)gw * D_IN;
    float acc[NE];
#pragma unroll
    for (int e = 0; e < NE; e++) acc[e] = 0.f;

    for (int d = lane; d < D_IN; d += 32) {
        float xv = xr[d];
        float4 a = *(const float4*)(Wr + d * NE);
        float4 b = *(const float4*)(Wr + d * NE + 4);
        acc[0] += xv * a.x; acc[1] += xv * a.y; acc[2] += xv * a.z; acc[3] += xv * a.w;
        acc[4] += xv * b.x; acc[5] += xv * b.y; acc[6] += xv * b.z; acc[7] += xv * b.w;
    }
#pragma unroll
    for (int e = 0; e < NE; e++) {
#pragma unroll
        for (int o = 16; o > 0; o >>= 1)
            acc[e] += __shfl_xor_sync(0xffffffffu, acc[e], o);
    }
    if (lane == 0) {
        float lg[NE];
#pragma unroll
        for (int e = 0; e < NE; e++) lg[e] = acc[e] + br[e];
        int i0 = 0;
#pragma unroll
        for (int e = 1; e < NE; e++) if (lg[e] > lg[i0]) i0 = e;
        int i1 = (i0 == 0) ? 1 : 0;
#pragma unroll
        for (int e = 0; e < NE; e++) if (e != i0 && lg[e] > lg[i1]) i1 = e;
        float ex  = expf(lg[i1] - lg[i0]);
        float inv = 1.0f / (1.0f + ex);
        g_top[2 * gw + 0] = i0;  g_top[2 * gw + 1] = i1;
        g_wt [2 * gw + 0] = inv; g_wt [2 * gw + 1] = ex * inv;
        atomicAdd(&g_cnt[i0], 1);
        atomicAdd(&g_cnt[i1], 1);
    }
}

// ---------------------------------------------------------------------------
// scan + fill fused: single block (thread 0 scans, then all threads pack)
// ---------------------------------------------------------------------------
__global__ void scanfill_kernel() {
    if (threadIdx.x == 0) {
        int s = 0;
        for (int e = 0; e < NE; e++) { g_off[e] = s; s += g_cnt[e]; }
    }
    __syncthreads();
    for (int t = threadIdx.x; t < T_TOK; t += blockDim.x) {
#pragma unroll
        for (int s = 0; s < 2; s++) {
            int e = g_top[2 * t + s];
            int p = g_off[e] + atomicAdd(&g_fill[e], 1);
            g_tok[p] = t;
            g_pw[p]  = g_wt[2 * t + s];
        }
    }
}

// ---------------------------------------------------------------------------
// launch: memset(1) prep(2) router(3) scanfill(4) FFN1(5=profiled) FFN2(6)
// ---------------------------------------------------------------------------
extern "C" void kernel_launch(void* const* d_in, const int* in_sizes, int n_in,
                              void* d_out, int out_size) {
    const float* x   = (const float*)d_in[0];
    const float* Wr  = (const float*)d_in[1];
    const float* br  = (const float*)d_in[2];
    const float* W1  = (const float*)d_in[3];
    const float* b1  = (const float*)d_in[4];
    const float* W2  = (const float*)d_in[5];
    const float* b2  = (const float*)d_in[6];
    float*       out = (float*)d_out;

    cudaFuncSetAttribute(moe_mma_kernel<1024, 4096, true>,
                         cudaFuncAttributeMaxDynamicSharedMemorySize, SMEM_BYTES);
    cudaFuncSetAttribute(moe_mma_kernel<4096, 1024, false>,
                         cudaFuncAttributeMaxDynamicSharedMemorySize, SMEM_BYTES);

    __half *w1f, *w2f;
    cudaGetSymbolAddress((void**)&w1f, g_w1f);
    cudaGetSymbolAddress((void**)&w2f, g_w2f);

    cudaMemsetAsync(out, 0, (size_t)out_size * sizeof(float));
    prep_kernel<<<2048, 256>>>(x, W1, W2);
    router_kernel<<<T_TOK / 8, 256>>>(x, Wr, br);
    scanfill_kernel<<<1, 256>>>();

    // FFN1: h = relu(x_g @ W1 + b1) -> g_hf; K=1024
    moe_mma_kernel<1024, 4096, true>
        <<<dim3(D_FF / 128, T_TOK / 128, NE), 256, SMEM_BYTES>>>(w1f, b1, out);
    // FFN2: out += w * (h @ W2 + b2); K=4096
    moe_mma_kernel<4096, 1024, false>
        <<<dim3(D_IN / 128, T_TOK / 128, NE), 256, SMEM_BYTES>>>(w2f, b2, out);
}